// round 5
// baseline (speedup 1.0000x reference)
#include <cuda_runtime.h>

#define DIM      4096
#define B        8
#define KV_DIM   1024   // N_KV_HEADS * HEAD_DIM
#define TOTAL    16384

// Scratch (allocation-free rule: __device__ globals)
__device__ __align__(16) float g_x[B * KV_DIM];  // up-proj result  [b][r]
__device__ __align__(16) float g_y[B * DIM];     // down-proj result [b][o]

__device__ __forceinline__ float dot4(float4 a, float4 b) {
    return a.x * b.x + a.y * b.y + a.z * b.z + a.w * b.w;
}

// ---------------------------------------------------------------------------
// Kernel 1: x[b][r] = sum_k emb[b][k] * Wup[r][k]
// grid = 1024 (one block per output feature r), 128 threads.
// W row (16 KB/block) is the only DRAM traffic; emb (128 KB) is L1/L2-hot.
// All 8 W float4s are prefetched into registers (MLP=8) before any FMA.
// ---------------------------------------------------------------------------
__global__ void __launch_bounds__(128) up_proj_kernel(
    const float* __restrict__ emb, const float* __restrict__ Wup)
{
    const int r   = blockIdx.x;      // 0..1023
    const int tid = threadIdx.x;
    const float4* w4 = reinterpret_cast<const float4*>(Wup + (size_t)r * DIM);

    // Front-batch the DRAM loads: 8 independent LDG.128 in flight.
    float4 w[8];
#pragma unroll
    for (int k = 0; k < 8; k++) w[k] = __ldg(&w4[tid + k * 128]);

    float acc[B];
#pragma unroll
    for (int b = 0; b < B; b++) acc[b] = 0.f;

#pragma unroll
    for (int k = 0; k < 8; k++) {
        const int q = tid + k * 128;
        // Batch the 8 cached emb loads, then 8 independent FMA chains.
        float4 e[B];
#pragma unroll
        for (int b = 0; b < B; b++)
            e[b] = __ldg(reinterpret_cast<const float4*>(emb + (size_t)b * DIM) + q);
#pragma unroll
        for (int b = 0; b < B; b++) acc[b] += dot4(w[k], e[b]);
    }

    __shared__ float s_part[B * 4];
#pragma unroll
    for (int b = 0; b < B; b++) {
        float v = acc[b];
#pragma unroll
        for (int off = 16; off; off >>= 1) v += __shfl_down_sync(0xffffffffu, v, off);
        if ((tid & 31) == 0) s_part[b * 4 + (tid >> 5)] = v;
    }
    __syncthreads();
    if (tid < B) {
        const float v = s_part[tid * 4 + 0] + s_part[tid * 4 + 1]
                      + s_part[tid * 4 + 2] + s_part[tid * 4 + 3];
        g_x[tid * KV_DIM + r] = v;
    }
}

// ---------------------------------------------------------------------------
// Kernel 2: y[b][o] = sum_j val[b][j] * Wdown[o][j]
//   val[b][j] = x[b][ ((j>>9)<<7) | (j&127) ]   (repeat-interleave remap)
// grid = 4096 (one block per output feature o), 128 threads.
// Wdown (64 MB) read exactly once; g_x (32 KB) is L1-resident.
// Same register-prefetch structure as kernel 1.
// ---------------------------------------------------------------------------
__global__ void __launch_bounds__(128) down_proj_kernel(
    const float* __restrict__ Wdown)
{
    const int o   = blockIdx.x;      // 0..4095
    const int tid = threadIdx.x;
    const float4* w4 = reinterpret_cast<const float4*>(Wdown + (size_t)o * DIM);

    float4 w[8];
#pragma unroll
    for (int k = 0; k < 8; k++) w[k] = __ldg(&w4[tid + k * 128]);

    float acc[B];
#pragma unroll
    for (int b = 0; b < B; b++) acc[b] = 0.f;

#pragma unroll
    for (int k = 0; k < 8; k++) {
        const int q  = tid + k * 128;
        const int j0 = 4 * q;
        const int m0 = ((j0 >> 9) << 7) | (j0 & 127);   // remapped, float4-aligned
        float4 v[B];
#pragma unroll
        for (int b = 0; b < B; b++)
            v[b] = *reinterpret_cast<const float4*>(&g_x[b * KV_DIM + m0]);
#pragma unroll
        for (int b = 0; b < B; b++) acc[b] += dot4(w[k], v[b]);
    }

    __shared__ float s_part[B * 4];
#pragma unroll
    for (int b = 0; b < B; b++) {
        float v = acc[b];
#pragma unroll
        for (int off = 16; off; off >>= 1) v += __shfl_down_sync(0xffffffffu, v, off);
        if ((tid & 31) == 0) s_part[b * 4 + (tid >> 5)] = v;
    }
    __syncthreads();
    if (tid < B) {
        const float v = s_part[tid * 4 + 0] + s_part[tid * 4 + 1]
                      + s_part[tid * 4 + 2] + s_part[tid * 4 + 3];
        g_y[tid * DIM + o] = v;
    }
}

// ---------------------------------------------------------------------------
// Kernel 3: out[t][:] = y[batch(t)][:]   — the 256 MB broadcast (HBM-write-bound)
// grid = 4096 blocks x 128 threads, 4 tokens per block, 8 float4/thread/token.
// y (128 KB) becomes L1-resident per SM; streaming stores for the output.
// ---------------------------------------------------------------------------
__global__ void __launch_bounds__(128) broadcast_kernel(
    const int* __restrict__ seqlen_raw, float* __restrict__ out)
{
    __shared__ int s_off[B + 1];
    if (threadIdx.x == 0) {
        int sum32 = 0;
#pragma unroll
        for (int i = 0; i < B; i++) sum32 += seqlen_raw[i];
        const bool is64 = (sum32 != TOTAL);   // int64: low word at index 2*i (LE)
        int acc = 0;
#pragma unroll
        for (int i = 0; i < B; i++) {
            s_off[i] = acc;
            acc += is64 ? seqlen_raw[2 * i] : seqlen_raw[i];
        }
        s_off[B] = acc;
    }
    __syncthreads();

    const int tid = threadIdx.x;
#pragma unroll
    for (int t = 0; t < 4; t++) {
        const int token = blockIdx.x * 4 + t;
        int b = 0;
#pragma unroll
        for (int i = 1; i < B; i++) b += (token >= s_off[i]);

        const float4* y4 = reinterpret_cast<const float4*>(&g_y[b * DIM]);
        float4* o4 = reinterpret_cast<float4*>(out + (size_t)token * DIM);
#pragma unroll
        for (int k = 0; k < 8; k++) {
            const int q = tid + k * 128;
            __stcs(&o4[q], __ldg(&y4[q]));
        }
    }
}

// ---------------------------------------------------------------------------
// Inputs (metadata order): embedding [8,4096] f32, W_up [1024,4096] f32,
// W_down [4096,4096] f32, seqlen [8] int. Output: [16384,4096] f32.
// ---------------------------------------------------------------------------
extern "C" void kernel_launch(void* const* d_in, const int* in_sizes, int n_in,
                              void* d_out, int out_size)
{
    const float* emb    = (const float*)d_in[0];
    const float* Wup    = (const float*)d_in[1];
    const float* Wdown  = (const float*)d_in[2];
    const int*   seqlen = (const int*)d_in[3];
    float* out = (float*)d_out;

    up_proj_kernel<<<KV_DIM, 128>>>(emb, Wup);
    down_proj_kernel<<<DIM, 128>>>(Wdown);
    broadcast_kernel<<<TOTAL / 4, 128>>>(seqlen, out);
}

// round 6
// speedup vs baseline: 1.0264x; 1.0264x over previous
#include <cuda_runtime.h>

#define DIM      4096
#define B        8
#define KV_DIM   1024   // N_KV_HEADS * HEAD_DIM
#define TOTAL    16384
#define O_TILE   16     // output columns per fused block

// Scratch (allocation-free rule: __device__ globals)
__device__ __align__(16) float g_x[B * KV_DIM];  // up-proj result [b][r]

__device__ __forceinline__ float dot4(float4 a, float4 b) {
    return a.x * b.x + a.y * b.y + a.z * b.z + a.w * b.w;
}

// ---------------------------------------------------------------------------
// Kernel 1: x[b][r] = sum_k emb[b][k] * Wup[r][k]
// grid = 512 blocks, 2 W rows per block, 128 threads.
// Each emb float4 load now feeds TWO dot products (halves redundant L1 traffic).
// ---------------------------------------------------------------------------
__global__ void __launch_bounds__(128) up_proj_kernel(
    const float* __restrict__ emb, const float* __restrict__ Wup)
{
    const int r0  = 2 * blockIdx.x;  // rows r0, r0+1
    const int tid = threadIdx.x;
    const float4* w4 = reinterpret_cast<const float4*>(Wup);
    const float4* e4 = reinterpret_cast<const float4*>(emb);

    float acc[2][B];
#pragma unroll
    for (int i = 0; i < 2; i++)
#pragma unroll
        for (int b = 0; b < B; b++) acc[i][b] = 0.f;

#pragma unroll
    for (int k = 0; k < 8; k++) {
        const int q = tid + k * 128;
        const float4 w0 = __ldg(&w4[(size_t)r0 * 1024 + q]);
        const float4 w1 = __ldg(&w4[(size_t)(r0 + 1) * 1024 + q]);
#pragma unroll
        for (int b = 0; b < B; b++) {
            const float4 e = __ldg(&e4[(size_t)b * 1024 + q]);
            acc[0][b] += dot4(w0, e);
            acc[1][b] += dot4(w1, e);
        }
    }

    __shared__ float s_part[2][B][4];
#pragma unroll
    for (int i = 0; i < 2; i++)
#pragma unroll
        for (int b = 0; b < B; b++) {
            float v = acc[i][b];
#pragma unroll
            for (int off = 16; off; off >>= 1) v += __shfl_down_sync(0xffffffffu, v, off);
            if ((tid & 31) == 0) s_part[i][b][tid >> 5] = v;
        }
    __syncthreads();
    if (tid < 16) {
        const int row = tid >> 3, b = tid & 7;
        const float v = s_part[row][b][0] + s_part[row][b][1]
                      + s_part[row][b][2] + s_part[row][b][3];
        g_x[b * KV_DIM + r0 + row] = v;
    }
}

// ---------------------------------------------------------------------------
// Kernel 2 (FUSED down_proj + broadcast):
// Block owns O_TILE=16 output columns. grid = 4096/16 = 256 blocks, 256 thr.
//
// Phase A: y[b][o] = sum_j val[b][j] * Wdown[o][j] for the 16 columns.
//   val[b][j] = x[b][((j>>9)<<7)|(j&127)]  (repeat-interleave remap).
//   8 warps: warp = (khalf, rgroup); rgroup owns 4 rows (register blocking:
//   each x float4 feeds 16 FMAs), khalf splits the 4096-wide reduction.
//   Wdown (64 MB chip-wide) read exactly once from DRAM.
//
// Phase B: the 8x16 y-tile lives in REGISTERS (8 float4/thread); every thread
//   streams its float4 column to all tokens of each batch with __stcs.
//   y never round-trips through L2 -> LTS traffic drops from ~512MB to ~320MB.
// ---------------------------------------------------------------------------
__global__ void __launch_bounds__(256) fused_down_bcast_kernel(
    const float* __restrict__ Wdown, const int* __restrict__ seqlen_raw,
    float* __restrict__ out)
{
    const int tid  = threadIdx.x;
    const int lane = tid & 31;
    const int wid  = tid >> 5;
    const int o0   = blockIdx.x * O_TILE;

    // --- seqlen prefix (int32/int64 auto-detect), done once up front ---
    __shared__ int s_off[B + 1];
    if (tid == 0) {
        int sum32 = 0;
#pragma unroll
        for (int i = 0; i < B; i++) sum32 += seqlen_raw[i];
        const bool is64 = (sum32 != TOTAL);
        int acc = 0;
#pragma unroll
        for (int i = 0; i < B; i++) {
            s_off[i] = acc;
            acc += is64 ? seqlen_raw[2 * i] : seqlen_raw[i];
        }
        s_off[B] = acc;
    }

    // ---------------- Phase A: compute the 8 x 16 y-tile ----------------
    const int khalf = wid >> 2;          // 0..1 : which half of the reduction
    const int rg    = wid & 3;           // 0..3 : which 4-row group
    const int rbase = o0 + rg * 4;
    const float4* Wd4 = reinterpret_cast<const float4*>(Wdown);

    float acc[4][B];
#pragma unroll
    for (int i = 0; i < 4; i++)
#pragma unroll
        for (int b = 0; b < B; b++) acc[i][b] = 0.f;

#pragma unroll 4
    for (int s = 0; s < 16; s++) {
        const int q = khalf * 512 + s * 32 + lane;   // float4 index in [0,1024)
        float4 w[4];
#pragma unroll
        for (int i = 0; i < 4; i++)
            w[i] = __ldg(&Wd4[(size_t)(rbase + i) * 1024 + q]);
        const int j0 = 4 * q;
        const int m0 = ((j0 >> 9) << 7) | (j0 & 127);  // remap, float4-aligned
#pragma unroll
        for (int b = 0; b < B; b++) {
            const float4 xv = *reinterpret_cast<const float4*>(&g_x[b * KV_DIM + m0]);
#pragma unroll
            for (int i = 0; i < 4; i++) acc[i][b] += dot4(w[i], xv);
        }
    }

    __shared__ float s_part[2][O_TILE][B];
#pragma unroll
    for (int i = 0; i < 4; i++)
#pragma unroll
        for (int b = 0; b < B; b++) {
            float v = acc[i][b];
#pragma unroll
            for (int off = 16; off; off >>= 1) v += __shfl_down_sync(0xffffffffu, v, off);
            if (lane == 0) s_part[khalf][rg * 4 + i][b] = v;
        }
    __syncthreads();

    __shared__ __align__(16) float y_s[B][O_TILE];
    if (tid < 128) {
        const int row = tid >> 3, b = tid & 7;
        y_s[b][row] = s_part[0][row][b] + s_part[1][row][b];
    }
    __syncthreads();

    // ---------------- Phase B: broadcast tile to all tokens ----------------
    // thread -> (col4, lane64): col4 picks one float4 column of the tile,
    // lane64 picks token residue mod 64. yv[] stays in registers.
    const int col4   = tid & 3;
    const int lane64 = tid >> 2;

    float4 yv[B];
#pragma unroll
    for (int b = 0; b < B; b++)
        yv[b] = *reinterpret_cast<const float4*>(&y_s[b][col4 * 4]);

    float4* out4 = reinterpret_cast<float4*>(out) + (o0 >> 2) + col4;

#pragma unroll
    for (int b = 0; b < B; b++) {
        const float4 v  = yv[b];                    // compile-time index
        const int   lo  = s_off[b], hi = s_off[b + 1];
        // first token >= lo with token % 64 == lane64
        int t = lo + ((lane64 - lo) & 63);
        for (; t < hi; t += 64)
            __stcs(out4 + (size_t)t * 1024, v);
    }
}

// ---------------------------------------------------------------------------
// Inputs (metadata order): embedding [8,4096] f32, W_up [1024,4096] f32,
// W_down [4096,4096] f32, seqlen [8] int. Output: [16384,4096] f32.
// ---------------------------------------------------------------------------
extern "C" void kernel_launch(void* const* d_in, const int* in_sizes, int n_in,
                              void* d_out, int out_size)
{
    const float* emb    = (const float*)d_in[0];
    const float* Wup    = (const float*)d_in[1];
    const float* Wdown  = (const float*)d_in[2];
    const int*   seqlen = (const int*)d_in[3];
    float* out = (float*)d_out;

    up_proj_kernel<<<KV_DIM / 2, 128>>>(emb, Wup);
    fused_down_bcast_kernel<<<DIM / O_TILE, 256>>>(Wdown, seqlen, out);
}